// round 6
// baseline (speedup 1.0000x reference)
#include <cuda_runtime.h>
#include <cstdint>
#include <cstddef>

// Shapes (fixed by the problem)
#define B 16
#define W 256
#define S 512
#define H 768
#define L 12
#define E 256
#define NW (B * W)                  // 4096 words

#define GRID 296                    // persistent: 2 blocks per SM
#define NS 3                        // pipeline stages per block

#define LAYER_STRIDE ((size_t)B * S * H)
#define ROW_BYTES (H * 4)                   // 3072 B per (l,b,s) row
#define ROW_F4    (ROW_BYTES / 16)          // 192 float4 per row
#define STAGE_BYTES (L * ROW_BYTES)         // 36864 B = one span position, all 12 layers
#define SMEM_STAGES (NS * STAGE_BYTES)      // 110592
#define SMEM_TOTAL  (SMEM_STAGES + 64)      // + mbarriers

__device__ __forceinline__ uint32_t smem_u32(const void* p) {
    return (uint32_t)__cvta_generic_to_shared(p);
}

__device__ __forceinline__ void wait_full(uint32_t mbar, uint32_t parity) {
    uint32_t done;
    asm volatile(
        "{\n\t.reg .pred p;\n\t"
        "mbarrier.try_wait.parity.acquire.cta.shared::cta.b64 p, [%1], %2, 0x989680;\n\t"
        "selp.b32 %0, 1, 0, p;\n\t}"
        : "=r"(done) : "r"(mbar), "r"(parity) : "memory");
    if (!done) {
        asm volatile(
            "{\n\t.reg .pred P1;\n\t"
            "WL_%=:\n\t"
            "mbarrier.try_wait.parity.acquire.cta.shared::cta.b64 P1, [%0], %1, 0x989680;\n\t"
            "@P1 bra.uni WD_%=;\n\t"
            "bra.uni WL_%=;\n\t"
            "WD_%=:\n\t}"
            :: "r"(mbar), "r"(parity) : "memory");
    }
}

// Persistent pipelined kernel. 296 blocks x 192 threads.
// Unit of work = one (word, span-position): 12 layer-rows = 36864 B staged
// into one ring stage by thread 0 via cp.async.bulk. Ring depth 3 keeps
// 1-2 stages of bytes continuously in flight per block while a third is
// reduced; __syncthreads() after consumption lets thread 0 refill in place.
__global__ __launch_bounds__(192)
void bert_lexer_kernel(const int* __restrict__ word_indices,
                       const int* __restrict__ span_start,
                       const int* __restrict__ span_end,
                       const float* __restrict__ W_embed,
                       const float* __restrict__ hidden,
                       float* __restrict__ out)
{
    extern __shared__ __align__(16) char smem[];
    const uint32_t smem_base = smem_u32(smem);
    const uint32_t mbar0     = smem_base + SMEM_STAGES;

    const int tid = threadIdx.x;          // 0..191
    const int bx  = blockIdx.x;           // 0..295

    if (tid == 0) {
        #pragma unroll
        for (int s = 0; s < NS; ++s)
            asm volatile("mbarrier.init.shared.b64 [%0], 1;"
                         :: "r"(mbar0 + 8u * s) : "memory");
        asm volatile("fence.proxy.async.shared::cta;" ::: "memory");
    }
    __syncthreads();

    // ---- producer cursor (thread 0 only) ----
    int p_word = bx, p_pos = 0, p_s0 = 0, p_len = 0;
    if (tid == 0 && p_word < NW) {
        p_s0  = span_start[p_word];
        p_len = span_end[p_word] - p_s0;
    }

    auto issue = [&](int st) {
        const uint32_t full = mbar0 + 8u * st;
        asm volatile("mbarrier.arrive.expect_tx.shared.b64 _, [%0], %1;"
                     :: "r"(full), "n"(STAGE_BYTES) : "memory");
        const float* row = hidden + ((size_t)(p_word >> 8) * S
                                     + (size_t)(p_s0 + p_pos)) * H;
        uint32_t dst = smem_base + (uint32_t)st * STAGE_BYTES;
        #pragma unroll
        for (int l = 0; l < L; ++l) {
            asm volatile(
                "cp.async.bulk.shared::cta.global.mbarrier::complete_tx::bytes "
                "[%0], [%1], %2, [%3];"
                :: "r"(dst + (uint32_t)l * ROW_BYTES),
                   "l"(row + (size_t)l * LAYER_STRIDE),
                   "n"(ROW_BYTES), "r"(full) : "memory");
        }
        // advance cursor
        if (++p_pos == p_len) {
            p_word += GRID; p_pos = 0;
            if (p_word < NW) {
                p_s0  = span_start[p_word];
                p_len = span_end[p_word] - p_s0;
            }
        }
    };

    // ---- prologue: fill the ring ----
    if (tid == 0) {
        #pragma unroll
        for (int k = 0; k < NS; ++k)
            if (p_word < NW) issue(k);
    }

    // ---- main loop ----
    int unit = 0;
    for (int w = bx; w < NW; w += GRID) {
        const int s0  = span_start[w];
        const int len = span_end[w] - s0;       // 1 or 2
        float* orow = out + (size_t)w * (E + H);

        // word embedding gather overlaps pipeline waits
        if (tid < 64) {
            const int wi = word_indices[w];
            float4 ev = *(reinterpret_cast<const float4*>(
                              W_embed + (size_t)wi * E) + tid);
            __stcs(reinterpret_cast<float4*>(orow) + tid, ev);
        }

        float4 acc = make_float4(0.f, 0.f, 0.f, 0.f);
        for (int p = 0; p < len; ++p) {
            const int st = unit % NS;
            const uint32_t par = (uint32_t)((unit / NS) & 1);
            wait_full(mbar0 + 8u * st, par);

            const float4* sp = reinterpret_cast<const float4*>(
                                   smem + (size_t)st * STAGE_BYTES) + tid;
            #pragma unroll
            for (int l = 0; l < L; ++l) {
                float4 v = sp[l * ROW_F4];
                acc.x += v.x; acc.y += v.y; acc.z += v.z; acc.w += v.w;
            }
            __syncthreads();                  // all reads of stage st done
            if (tid == 0 && p_word < NW) issue(st);   // refill in place
            ++unit;
        }

        const float inv = 1.0f / (12.0f * (float)len);
        float4 r;
        r.x = acc.x * inv; r.y = acc.y * inv;
        r.z = acc.z * inv; r.w = acc.w * inv;
        __stcs(reinterpret_cast<float4*>(orow + E) + tid, r);
    }
}

extern "C" void kernel_launch(void* const* d_in, const int* in_sizes, int n_in,
                              void* d_out, int out_size)
{
    const int*   word_indices = (const int*)  d_in[0];   // [B, W]
    const int*   span_start   = (const int*)  d_in[1];   // [B, W]
    const int*   span_end     = (const int*)  d_in[2];   // [B, W]
    const float* W_embed      = (const float*)d_in[3];   // [V, E]
    const float* hidden       = (const float*)d_in[4];   // [L, B, S, H]
    float*       out          = (float*)      d_out;     // [B, W, E+H]

    (void)in_sizes; (void)n_in; (void)out_size;

    cudaFuncSetAttribute(bert_lexer_kernel,
                         cudaFuncAttributeMaxDynamicSharedMemorySize, SMEM_TOTAL);

    bert_lexer_kernel<<<GRID, 192, SMEM_TOTAL>>>(word_indices, span_start,
                                                 span_end, W_embed, hidden, out);
}

// round 7
// speedup vs baseline: 1.0375x; 1.0375x over previous
#include <cuda_runtime.h>
#include <cstdint>
#include <cstddef>

// Shapes (fixed by the problem)
#define B 16
#define W 256
#define S 512
#define H 768
#define L 12
#define E 256

#define LAYER_STRIDE ((size_t)B * S * H)   // elements between layers
#define ROW_BYTES (H * 4)                  // 3072 bytes per (l,b,s) row
#define ROW_F4    (ROW_BYTES / 16)         // 192 float4 per row
#define MAX_SLOTS (2 * L)                  // up to 24 staged rows (len<=2)
#define SMEM_ROWS_BYTES (MAX_SLOTS * ROW_BYTES)   // 73728
#define SMEM_TOTAL (SMEM_ROWS_BYTES + 16)         // + mbarrier

__device__ __forceinline__ uint32_t smem_u32(const void* p) {
    return (uint32_t)__cvta_generic_to_shared(p);
}

// One block per (b,w) word, 192 threads.
// Thread 0 issues 12 bulk copies (one per layer) of the word's span —
// len*3072 contiguous bytes each, since span positions s0..s1-1 are adjacent
// rows. Completion via mbarrier transaction bytes. Threads [0,64) overlap the
// word-embedding gather. After the barrier flips, all 192 threads reduce
// their float4 column across the 12*len staged rows.
__global__ __launch_bounds__(192)
void bert_lexer_kernel(const int* __restrict__ word_indices,
                       const int* __restrict__ span_start,
                       const int* __restrict__ span_end,
                       const float* __restrict__ W_embed,
                       const float* __restrict__ hidden,
                       float* __restrict__ out)
{
    extern __shared__ __align__(16) char smem[];
    uint64_t* mbar = reinterpret_cast<uint64_t*>(smem + SMEM_ROWS_BYTES);
    const uint32_t mbar_addr = smem_u32(mbar);

    const int bw  = blockIdx.x;            // 0 .. B*W-1
    const int b   = bw >> 8;               // W = 256
    const int tid = threadIdx.x;           // 0 .. 191

    const int s0  = span_start[bw];
    const int len = span_end[bw] - s0;     // 1 or 2

    if (tid == 0) {
        asm volatile("mbarrier.init.shared.b64 [%0], 1;" :: "r"(mbar_addr) : "memory");
        asm volatile("fence.proxy.async.shared::cta;" ::: "memory");
    }
    __syncthreads();

    if (tid == 0) {
        const uint32_t span_bytes = (uint32_t)len * ROW_BYTES;   // 3072 or 6144
        const uint32_t nbytes = (uint32_t)L * span_bytes;
        asm volatile("mbarrier.arrive.expect_tx.shared.b64 _, [%0], %1;"
                     :: "r"(mbar_addr), "r"(nbytes) : "memory");
        const float* row0 = hidden + ((size_t)b * S + (size_t)s0) * H;
        uint32_t dst = smem_u32(smem);
        #pragma unroll
        for (int l = 0; l < L; ++l) {
            // one contiguous copy: all span rows of layer l
            asm volatile(
                "cp.async.bulk.shared::cta.global.mbarrier::complete_tx::bytes "
                "[%0], [%1], %2, [%3];"
                :: "r"(dst), "l"(row0 + (size_t)l * LAYER_STRIDE),
                   "r"(span_bytes), "r"(mbar_addr) : "memory");
            dst += span_bytes;
        }
    }

    // ---- overlap: word embedding gather (threads 0..63) ----
    float* orow = out + (size_t)bw * (E + H);
    if (tid < 64) {
        const int wi = word_indices[bw];
        float4 ev = *(reinterpret_cast<const float4*>(W_embed + (size_t)wi * E) + tid);
        __stcs(reinterpret_cast<float4*>(orow) + tid, ev);
    }

    // ---- wait for all staged rows (acquire) ----
    {
        uint32_t done;
        asm volatile(
            "{\n\t.reg .pred p;\n\t"
            "mbarrier.try_wait.parity.acquire.cta.shared::cta.b64 p, [%1], %2, 0x989680;\n\t"
            "selp.b32 %0, 1, 0, p;\n\t}"
            : "=r"(done) : "r"(mbar_addr), "r"(0u) : "memory");
        if (!done) {
            asm volatile(
                "{\n\t.reg .pred P1;\n\t"
                "WAIT_LOOP:\n\t"
                "mbarrier.try_wait.parity.acquire.cta.shared::cta.b64 P1, [%0], %1, 0x989680;\n\t"
                "@P1 bra.uni WAIT_DONE;\n\t"
                "bra.uni WAIT_LOOP;\n\t"
                "WAIT_DONE:\n\t}"
                :: "r"(mbar_addr), "r"(0u) : "memory");
        }
    }

    // ---- reduce: each thread sums its float4 across 12*len staged rows ----
    const int nslots = L * len;            // 12 or 24
    const float4* sp = reinterpret_cast<const float4*>(smem) + tid;
    float4 acc = make_float4(0.f, 0.f, 0.f, 0.f);
    #pragma unroll 6
    for (int i = 0; i < nslots; ++i) {
        float4 v = sp[(size_t)i * ROW_F4];
        acc.x += v.x; acc.y += v.y; acc.z += v.z; acc.w += v.w;
    }

    const float inv = 1.0f / (12.0f * (float)len);
    float4 r;
    r.x = acc.x * inv; r.y = acc.y * inv; r.z = acc.z * inv; r.w = acc.w * inv;
    __stcs(reinterpret_cast<float4*>(orow + E) + tid, r);
}

extern "C" void kernel_launch(void* const* d_in, const int* in_sizes, int n_in,
                              void* d_out, int out_size)
{
    const int*   word_indices = (const int*)  d_in[0];   // [B, W]
    const int*   span_start   = (const int*)  d_in[1];   // [B, W]
    const int*   span_end     = (const int*)  d_in[2];   // [B, W]
    const float* W_embed      = (const float*)d_in[3];   // [V, E]
    const float* hidden       = (const float*)d_in[4];   // [L, B, S, H]
    float*       out          = (float*)      d_out;     // [B, W, E+H]

    (void)in_sizes; (void)n_in; (void)out_size;

    cudaFuncSetAttribute(bert_lexer_kernel,
                         cudaFuncAttributeMaxDynamicSharedMemorySize, SMEM_TOTAL);

    bert_lexer_kernel<<<B * W, 192, SMEM_TOTAL>>>(word_indices, span_start,
                                                  span_end, W_embed, hidden, out);
}

// round 8
// speedup vs baseline: 1.0483x; 1.0104x over previous
#include <cuda_runtime.h>
#include <cstdint>
#include <cstddef>

// Shapes (fixed by the problem)
#define B 16
#define W 256
#define S 512
#define H 768
#define L 12
#define E 256

#define LAYER_STRIDE ((size_t)B * S * H)     // elements between layers
#define HALF_FLOATS (H / 2)                  // 384 floats per half-row
#define HALF_BYTES  (HALF_FLOATS * 4)        // 1536 B per staged chunk
#define HALF_F4     (HALF_FLOATS / 4)        // 96 float4 per half-row
#define MAX_SLOTS   (2 * L)                  // up to 24 staged chunks (len<=2)
#define SMEM_ROWS_BYTES (MAX_SLOTS * HALF_BYTES)  // 36864
#define SMEM_TOTAL (SMEM_ROWS_BYTES + 16)         // + mbarrier -> 6 blocks/SM

__device__ __forceinline__ uint32_t smem_u32(const void* p) {
    return (uint32_t)__cvta_generic_to_shared(p);
}

// Two blocks per (b,w) word: blockIdx.x = bw*2 + half. 96 threads each.
// Thread 0 issues 12*len bulk copies of 1536 B (this half of each layer row)
// -> 6 independent copy streams per SM, ~220 KB/SM in flight, fine-grained
// channel interleave. half==0 block also does the word-embedding gather,
// overlapping the copy wait. After the mbarrier flips, 96 threads reduce
// their float4 column across the staged chunks.
__global__ __launch_bounds__(96)
void bert_lexer_kernel(const int* __restrict__ word_indices,
                       const int* __restrict__ span_start,
                       const int* __restrict__ span_end,
                       const float* __restrict__ W_embed,
                       const float* __restrict__ hidden,
                       float* __restrict__ out)
{
    extern __shared__ __align__(16) char smem[];
    const uint32_t mbar_addr = smem_u32(smem + SMEM_ROWS_BYTES);

    const int bx   = blockIdx.x;           // 0 .. 2*B*W-1
    const int bw   = bx >> 1;              // word id
    const int half = bx & 1;               // 0: h[0,384), 1: h[384,768)
    const int b    = bw >> 8;              // W = 256
    const int tid  = threadIdx.x;          // 0 .. 95

    const int s0  = span_start[bw];
    const int len = span_end[bw] - s0;     // 1 or 2

    if (tid == 0) {
        asm volatile("mbarrier.init.shared.b64 [%0], 1;" :: "r"(mbar_addr) : "memory");
        asm volatile("fence.proxy.async.shared::cta;" ::: "memory");
    }
    __syncthreads();

    if (tid == 0) {
        const int nchunks = L * len;                     // 12 or 24
        const uint32_t nbytes = (uint32_t)nchunks * HALF_BYTES;
        asm volatile("mbarrier.arrive.expect_tx.shared.b64 _, [%0], %1;"
                     :: "r"(mbar_addr), "r"(nbytes) : "memory");
        // base of this half within row (b, s0)
        const float* base = hidden + ((size_t)b * S + (size_t)s0) * H
                                   + (size_t)half * HALF_FLOATS;
        uint32_t dst = smem_u32(smem);
        #pragma unroll
        for (int l = 0; l < L; ++l) {
            const float* src = base + (size_t)l * LAYER_STRIDE;
            asm volatile(
                "cp.async.bulk.shared::cta.global.mbarrier::complete_tx::bytes "
                "[%0], [%1], %2, [%3];"
                :: "r"(dst), "l"(src), "n"(HALF_BYTES), "r"(mbar_addr) : "memory");
            dst += HALF_BYTES;
            if (len == 2) {
                asm volatile(
                    "cp.async.bulk.shared::cta.global.mbarrier::complete_tx::bytes "
                    "[%0], [%1], %2, [%3];"
                    :: "r"(dst), "l"(src + H), "n"(HALF_BYTES), "r"(mbar_addr) : "memory");
                dst += HALF_BYTES;
            }
        }
    }

    // ---- overlap: word embedding gather (half==0 block, threads 0..63) ----
    float* orow = out + (size_t)bw * (E + H);
    if (half == 0 && tid < 64) {
        const int wi = word_indices[bw];
        float4 ev = *(reinterpret_cast<const float4*>(W_embed + (size_t)wi * E) + tid);
        __stcs(reinterpret_cast<float4*>(orow) + tid, ev);
    }

    // ---- wait for all staged chunks (acquire) ----
    {
        uint32_t done;
        asm volatile(
            "{\n\t.reg .pred p;\n\t"
            "mbarrier.try_wait.parity.acquire.cta.shared::cta.b64 p, [%1], %2, 0x989680;\n\t"
            "selp.b32 %0, 1, 0, p;\n\t}"
            : "=r"(done) : "r"(mbar_addr), "r"(0u) : "memory");
        if (!done) {
            asm volatile(
                "{\n\t.reg .pred P1;\n\t"
                "WAIT_LOOP:\n\t"
                "mbarrier.try_wait.parity.acquire.cta.shared::cta.b64 P1, [%0], %1, 0x989680;\n\t"
                "@P1 bra.uni WAIT_DONE;\n\t"
                "bra.uni WAIT_LOOP;\n\t"
                "WAIT_DONE:\n\t}"
                :: "r"(mbar_addr), "r"(0u) : "memory");
        }
    }

    // ---- reduce: each thread sums its float4 across 12*len chunks ----
    const int nchunks = L * len;
    const float4* sp = reinterpret_cast<const float4*>(smem) + tid;
    float4 acc = make_float4(0.f, 0.f, 0.f, 0.f);
    #pragma unroll 6
    for (int i = 0; i < nchunks; ++i) {
        float4 v = sp[(size_t)i * HALF_F4];
        acc.x += v.x; acc.y += v.y; acc.z += v.z; acc.w += v.w;
    }

    const float inv = 1.0f / (12.0f * (float)len);
    float4 r;
    r.x = acc.x * inv; r.y = acc.y * inv; r.z = acc.z * inv; r.w = acc.w * inv;
    __stcs(reinterpret_cast<float4*>(orow + E) + (size_t)half * HALF_F4 + tid, r);
}

extern "C" void kernel_launch(void* const* d_in, const int* in_sizes, int n_in,
                              void* d_out, int out_size)
{
    const int*   word_indices = (const int*)  d_in[0];   // [B, W]
    const int*   span_start   = (const int*)  d_in[1];   // [B, W]
    const int*   span_end     = (const int*)  d_in[2];   // [B, W]
    const float* W_embed      = (const float*)d_in[3];   // [V, E]
    const float* hidden       = (const float*)d_in[4];   // [L, B, S, H]
    float*       out          = (float*)      d_out;     // [B, W, E+H]

    (void)in_sizes; (void)n_in; (void)out_size;

    cudaFuncSetAttribute(bert_lexer_kernel,
                         cudaFuncAttributeMaxDynamicSharedMemorySize, SMEM_TOTAL);

    bert_lexer_kernel<<<2 * B * W, 96, SMEM_TOTAL>>>(word_indices, span_start,
                                                     span_end, W_embed, hidden, out);
}